// round 12
// baseline (speedup 1.0000x reference)
#include <cuda_runtime.h>
#include <stdint.h>

// ---------------- problem constants ----------------
#define B_   8
#define F_   64
#define E_   50000
#define CO_  128
#define KK_  320         // F*5 contraction dim (kappa' = q*64 + f ordering)
#define UE_  64          // edges per pipeline unit (MMA N)
#define NT_  256         // threads per CTA
#define UPB_ 782         // ceil(50000/64)
#define NU_  (UPB_ * B_) // total units
#define NSTEP_ 40        // 320 / 8 (tf32 K per MMA)

#define TMEM_A_  128     // A: cols 128..447 (D: 0..127, double-buffered 64+64)
#define WS_STR_  324     // W smem staging row stride (floats)
#define HDR_     4096
#define BUF_     81920   // one G buffer: 10 K-groups * 8KB
#define EP_OFF_  (HDR_ + 2 * BUF_)          // epilogue transpose buffer
#define EP_STR_  68                          // floats per row (16B-aligned rows)
#define SMEM_SZ_ (EP_OFF_ + CO_ * EP_STR_ * 4)   // 202,752 B

// idesc kind::tf32: c=F32, a=TF32, b=TF32, N=64 (8<<17), M=128 (8<<24)
#define IDESC64_ 0x8100910u

__device__ __align__(16) float g_xt[(size_t)B_ * E_ * F_];   // x transposed (B,E,F)
__device__ int g_idx64;

#if defined(__CUDA_ARCH_FEAT_SM103_ALL)
#define TC_OK_ 1
#else
#define TC_OK_ 0
#endif

// ---------------- PTX helpers (generic) ----------------
__device__ __forceinline__ uint32_t smem_u32(const void* p) {
    uint32_t a;
    asm("{ .reg .u64 t; cvta.to.shared.u64 t, %1; cvt.u32.u64 %0, t; }" : "=r"(a) : "l"(p));
    return a;
}
__device__ __forceinline__ uint32_t elect1() {
    uint32_t p;
    asm volatile("{ .reg .pred p; elect.sync _|p, 0xFFFFFFFF; selp.b32 %0, 1, 0, p; }" : "=r"(p));
    return p;
}
__device__ __forceinline__ float f2t(float x) {
    uint32_t u;
    asm("cvt.rna.tf32.f32 %0, %1;" : "=r"(u) : "f"(x));
    return __uint_as_float(u);
}

#define MB_INIT(mb, c)    asm volatile("mbarrier.init.shared.b64 [%0], %1;" :: "r"(mb), "r"(c) : "memory")
#define MB_INVAL(mb)      asm volatile("mbarrier.inval.shared.b64 [%0];" :: "r"(mb) : "memory")

#define MB_WAIT_PARITY(mb, ph) do {                                          \
    uint32_t _m = (mb), _p = (ph), _d;                                       \
    asm volatile("{ .reg .pred p; mbarrier.try_wait.parity.acquire.cta.shared::cta.b64 p, [%1], %2; selp.b32 %0,1,0,p; }" \
                 : "=r"(_d) : "r"(_m), "r"(_p) : "memory");                  \
    if (!_d) {                                                               \
        asm volatile("{ .reg .pred P1;\n"                                    \
            "WL_%=: mbarrier.try_wait.parity.acquire.cta.shared::cta.b64 P1, [%0], %1, 0x989680;\n" \
            "@P1 bra.uni WD_%=;\n bra.uni WL_%=;\nWD_%=: }"                  \
            :: "r"(_m), "r"(_p) : "memory");                                 \
    } } while (0)

// ---------------- tcgen05 helpers (sm_103a-only) ----------------
#if TC_OK_
#define TC_ALLOC(sa, n)   asm volatile("tcgen05.alloc.cta_group::1.sync.aligned.shared::cta.b32 [%0], %1;" :: "r"(sa), "r"(n) : "memory")
#define TC_RELINQ()       asm volatile("tcgen05.relinquish_alloc_permit.cta_group::1.sync.aligned;")
#define TC_DEALLOC(t, n)  asm volatile("tcgen05.dealloc.cta_group::1.sync.aligned.b32 %0, %1;" :: "r"(t), "r"(n))
#define TC_WAIT_ST()      asm volatile("tcgen05.wait::st.sync.aligned;" ::: "memory")
#define TC_WAIT_LD()      asm volatile("tcgen05.wait::ld.sync.aligned;" ::: "memory")
#define TC_FENCE_BEFORE() asm volatile("tcgen05.fence::before_thread_sync;" ::: "memory")
#define TC_FENCE_AFTER()  asm volatile("tcgen05.fence::after_thread_sync;" ::: "memory")
#define TC_COMMIT(mb)     asm volatile("tcgen05.commit.cta_group::1.mbarrier::arrive::one.shared::cluster.b64 [%0];" :: "r"(mb) : "memory")

#define TC_ST_X32(addr, r) \
    asm volatile("tcgen05.st.sync.aligned.32x32b.x32.b32 [%0], "             \
        "{%1,%2,%3,%4,%5,%6,%7,%8,%9,%10,%11,%12,%13,%14,%15,%16,"          \
        "%17,%18,%19,%20,%21,%22,%23,%24,%25,%26,%27,%28,%29,%30,%31,%32};" \
        :: "r"(addr),                                                        \
        "r"((r)[0]),"r"((r)[1]),"r"((r)[2]),"r"((r)[3]),"r"((r)[4]),"r"((r)[5]),"r"((r)[6]),"r"((r)[7]), \
        "r"((r)[8]),"r"((r)[9]),"r"((r)[10]),"r"((r)[11]),"r"((r)[12]),"r"((r)[13]),"r"((r)[14]),"r"((r)[15]), \
        "r"((r)[16]),"r"((r)[17]),"r"((r)[18]),"r"((r)[19]),"r"((r)[20]),"r"((r)[21]),"r"((r)[22]),"r"((r)[23]), \
        "r"((r)[24]),"r"((r)[25]),"r"((r)[26]),"r"((r)[27]),"r"((r)[28]),"r"((r)[29]),"r"((r)[30]),"r"((r)[31]) \
        : "memory")

#define TC_LD_X32(r, addr) \
    asm volatile("tcgen05.ld.sync.aligned.32x32b.x32.b32 "                   \
        "{%0,%1,%2,%3,%4,%5,%6,%7,%8,%9,%10,%11,%12,%13,%14,%15,"           \
        "%16,%17,%18,%19,%20,%21,%22,%23,%24,%25,%26,%27,%28,%29,%30,%31}, [%32];" \
        : "=r"((r)[0]),"=r"((r)[1]),"=r"((r)[2]),"=r"((r)[3]),"=r"((r)[4]),"=r"((r)[5]),"=r"((r)[6]),"=r"((r)[7]), \
        "=r"((r)[8]),"=r"((r)[9]),"=r"((r)[10]),"=r"((r)[11]),"=r"((r)[12]),"=r"((r)[13]),"=r"((r)[14]),"=r"((r)[15]), \
        "=r"((r)[16]),"=r"((r)[17]),"=r"((r)[18]),"=r"((r)[19]),"=r"((r)[20]),"=r"((r)[21]),"=r"((r)[22]),"=r"((r)[23]), \
        "=r"((r)[24]),"=r"((r)[25]),"=r"((r)[26]),"=r"((r)[27]),"=r"((r)[28]),"=r"((r)[29]),"=r"((r)[30]),"=r"((r)[31]) \
        : "r"(addr))

__device__ __forceinline__ void mma_tf32_ts(uint32_t d, uint32_t a, uint64_t bdesc,
                                            uint32_t idesc, bool acc) {
    uint32_t en = acc ? 1u : 0u;
    asm volatile(
        "{\n\t.reg .pred p;\n\tsetp.ne.u32 p, %5, 0;\n\t"
        "tcgen05.mma.cta_group::1.kind::tf32 [%0], [%1], %2, %3, {%4, %4, %4, %4}, p;\n\t}"
        :: "r"(d), "r"(a), "l"(bdesc), "r"(idesc), "r"(0u), "r"(en) : "memory");
}
#endif // TC_OK_

// SW128 smem descriptor: layout=SW128(2), version=1, SBO=64, LBO=1
#define DESC_BASE_ ((2ull << 61) | (1ull << 46) | (64ull << 32) | (1ull << 16))
#define MAKE_DESC(a) (DESC_BASE_ | ((uint64_t)((a) >> 4) & 0x3FFF))
#define SWZ(o) ((o) ^ (((o) >> 3) & 0x70))

// ---------------------------------------------------------------------------
// x (B,F,E) -> xt (B,E,F); block (0,0) also detects gemm dtype.
// ---------------------------------------------------------------------------
__global__ __launch_bounds__(256) void transpose_kernel(const float* __restrict__ x,
                                                        const unsigned int* __restrict__ g) {
    __shared__ float t[64 * 68];
    __shared__ int s_nz;
    int b  = blockIdx.y;
    int e0 = blockIdx.x * 64;
    int tid = threadIdx.x;

    if (blockIdx.x == 0 && blockIdx.y == 0) {
        if (tid == 0) s_nz = 0;
        __syncthreads();
        unsigned acc = 0;
        #pragma unroll
        for (int i = 0; i < 8; i++) acc |= g[(tid + i * 256) * 2 + 1];
        if (acc) atomicOr(&s_nz, 1);
        __syncthreads();
        if (tid == 0) g_idx64 = (s_nz == 0) ? 1 : 0;
        __syncthreads();
    }

    if (e0 + 64 <= E_) {
        #pragma unroll
        for (int i = 0; i < 4; i++) {
            int idx = tid + i * 256;
            int f = idx >> 4, c4 = idx & 15;
            float4 v = *(const float4*)(x + ((size_t)b * F_ + f) * E_ + e0 + c4 * 4);
            *(float4*)(&t[f * 68 + c4 * 4]) = v;
        }
        __syncthreads();
        int e  = tid & 63;
        int jb = tid >> 6;
        float* po = g_xt + ((size_t)b * E_ + e0 + e) * F_;
        #pragma unroll
        for (int jj = 0; jj < 4; jj++) {
            int j = jb + jj * 4;
            float4 v = make_float4(t[(j*4+0)*68 + e], t[(j*4+1)*68 + e],
                                   t[(j*4+2)*68 + e], t[(j*4+3)*68 + e]);
            *(float4*)(po + j * 4) = v;
        }
    } else {
        for (int idx = tid; idx < 64 * 64; idx += 256) {
            int e = e0 + (idx & 63);
            int f = idx >> 6;
            if (e < E_)
                g_xt[((size_t)b * E_ + e) * F_ + f] = x[((size_t)b * F_ + f) * E_ + e];
        }
    }
}

// ---------------------------------------------------------------------------
// Persistent pipelined tcgen05 kernel: 64-edge units, double-buffered G + D.
// ---------------------------------------------------------------------------
__global__ __launch_bounds__(NT_, 1)
void meshconv_tc(const void*  __restrict__ gemm_raw,
                 const float* __restrict__ Wg,
                 const float* __restrict__ bias,
                 float*       __restrict__ out)
{
#if TC_OK_
    extern __shared__ char smem[];
    uint32_t sbase = smem_u32(smem);
    char*  tile = smem + HDR_;
    float* ep   = (float*)(smem + EP_OFF_);
    uint32_t mbar0 = sbase + 8;     // slot 0
    uint32_t mbar1 = sbase + 16;    // slot 1
    uint32_t gsb   = sbase + HDR_;

    const int tid = threadIdx.x, wid = tid >> 5, lane = tid & 31;
    const int idx64 = g_idx64;

    if (wid == 0) {
        TC_ALLOC(sbase, 512);
        TC_RELINQ();
        if (elect1()) { MB_INIT(mbar0, 1); MB_INIT(mbar1, 1); }
    }
    __syncthreads();
    uint32_t tmem;
    asm volatile("ld.shared.b32 %0, [%1];" : "=r"(tmem) : "r"(sbase));

    // ---- stage W: gmem -> smem (kappa = f*5+q -> kappa' = q*64+f), one pass ----
    float* ws = (float*)tile;   // 166,912 B spans buf0+buf1+ep region (pre-pipeline only)
    #pragma unroll 4
    for (int i = 0; i < 40; i++) {
        int idx4 = tid + i * 256;
        int o = idx4 / 80, c4 = idx4 % 80;
        float4 v = *(const float4*)(Wg + o * KK_ + c4 * 4);
        int kk = c4 * 4;
        ws[o * WS_STR_ + ((kk    ) % 5) * 64 + (kk    ) / 5] = v.x;
        ws[o * WS_STR_ + ((kk + 1) % 5) * 64 + (kk + 1) / 5] = v.y;
        ws[o * WS_STR_ + ((kk + 2) % 5) * 64 + (kk + 2) / 5] = v.z;
        ws[o * WS_STR_ + ((kk + 3) % 5) * 64 + (kk + 3) / 5] = v.w;
    }
    __syncthreads();

    // ---- smem -> TMEM (A operand, tf32; lane = Cout row, col = kappa') ----
    if (tid < 128) {
        const float* wrow = ws + tid * WS_STR_;
        uint32_t woff = (uint32_t)(wid & 3) << 21;
        for (int g = 0; g < 10; g++) {
            uint32_t r[32];
            #pragma unroll
            for (int u = 0; u < 8; u++) {
                float4 v = *(const float4*)(wrow + g * 32 + u * 4);
                asm("cvt.rna.tf32.f32 %0, %1;" : "=r"(r[u*4+0]) : "f"(v.x));
                asm("cvt.rna.tf32.f32 %0, %1;" : "=r"(r[u*4+1]) : "f"(v.y));
                asm("cvt.rna.tf32.f32 %0, %1;" : "=r"(r[u*4+2]) : "f"(v.z));
                asm("cvt.rna.tf32.f32 %0, %1;" : "=r"(r[u*4+3]) : "f"(v.w));
            }
            TC_ST_X32(tmem + TMEM_A_ + g * 32 + woff, r);
            TC_WAIT_ST();
        }
    }
    TC_FENCE_BEFORE();
    __syncthreads();

    // ---- pipelined unit loop ----
    int prev_b = 0, prev_e0 = 0, prev_i = -1;
    int i = 0;
    for (int t = blockIdx.x; t < NU_; t += gridDim.x, i++) {
        int b  = t / UPB_;
        int e0 = (t - b * UPB_) * UE_;
        const float* xb = g_xt + (size_t)b * E_ * F_;
        int p = i & 1;
        char* buf = tile + p * BUF_;

        // ---- gather + combine -> G buffer p (tf32, SW128 atoms) ----
        #pragma unroll
        for (int ii = 0; ii < 4; ii++) {
            int u = tid + ii * 256;
            int e = u >> 4, c = u & 15;
            int eg = e0 + e; if (eg > E_ - 1) eg = E_ - 1;

            int n1, n2, n3, n4;
            if (idx64) {
                const long long* gp = (const long long*)gemm_raw + ((size_t)b * E_ + eg) * 4;
                n1 = (int)gp[0]; n2 = (int)gp[1]; n3 = (int)gp[2]; n4 = (int)gp[3];
            } else {
                int4 gi = *(const int4*)((const int*)gemm_raw + ((size_t)b * E_ + eg) * 4);
                n1 = gi.x; n2 = gi.y; n3 = gi.z; n4 = gi.w;
            }

            float4 v0 = *((const float4*)(xb + (size_t)eg * F_) + c);
            float4 v1 = *((const float4*)(xb + (size_t)n1 * F_) + c);
            float4 v2 = *((const float4*)(xb + (size_t)n2 * F_) + c);
            float4 v3 = *((const float4*)(xb + (size_t)n3 * F_) + c);
            float4 v4 = *((const float4*)(xb + (size_t)n4 * F_) + c);

            float4 w0 = make_float4(f2t(v0.x), f2t(v0.y), f2t(v0.z), f2t(v0.w));
            float4 w1 = make_float4(f2t(v1.x+v3.x), f2t(v1.y+v3.y), f2t(v1.z+v3.z), f2t(v1.w+v3.w));
            float4 w2 = make_float4(f2t(v2.x+v4.x), f2t(v2.y+v4.y), f2t(v2.z+v4.z), f2t(v2.w+v4.w));
            float4 w3 = make_float4(f2t(fabsf(v1.x-v3.x)), f2t(fabsf(v1.y-v3.y)),
                                    f2t(fabsf(v1.z-v3.z)), f2t(fabsf(v1.w-v3.w)));
            float4 w4 = make_float4(f2t(fabsf(v2.x-v4.x)), f2t(fabsf(v2.y-v4.y)),
                                    f2t(fabsf(v2.z-v4.z)), f2t(fabsf(v2.w-v4.w)));

            int half = c >> 3, i4 = c & 7;
            uint32_t obase = ((uint32_t)(e >> 3) << 10) + ((uint32_t)(e & 7) << 7)
                           + ((uint32_t)i4 << 4);
            #define PUTQ(q, val) do {                                         \
                uint32_t off = obase + (uint32_t)((2*(q) + half) << 13);      \
                off = SWZ(off);                                               \
                *(float4*)(buf + off) = (val);                                \
            } while (0)
            PUTQ(0, w0); PUTQ(1, w1); PUTQ(2, w2); PUTQ(3, w3); PUTQ(4, w4);
            #undef PUTQ
        }
        asm volatile("fence.proxy.async.shared::cta;" ::: "memory");
        __syncthreads();

        // ---- issue MMA for unit i (async): D cols p*64, buffer p ----
        if (wid == 0) {
            TC_FENCE_AFTER();
            if (elect1()) {
                uint64_t bb = MAKE_DESC(gsb + (uint32_t)p * BUF_);
                #pragma unroll 1
                for (int k = 0; k < NSTEP_; k++) {
                    uint64_t bd = bb + (uint64_t)((k >> 2) * 512 + (k & 3) * 2);
                    mma_tf32_ts(tmem + p * 64, tmem + TMEM_A_ + k * 8, bd, IDESC64_, k > 0);
                }
                TC_COMMIT(p ? mbar1 : mbar0);
            }
        }

        // ---- epilogue for unit i-1 (overlaps MMA(i)) ----
        if (prev_i >= 0) {
            int pp = prev_i & 1;
            MB_WAIT_PARITY(pp ? mbar1 : mbar0, (prev_i >> 1) & 1);
            TC_FENCE_AFTER();

            int h = wid >> 2;                    // 0..1 -> cols 0-31 / 32-63
            int o = (wid & 3) * 32 + lane;
            uint32_t r[32];
            TC_LD_X32(r, tmem + pp * 64 + h * 32);
            TC_WAIT_LD();
            TC_FENCE_BEFORE();
            float bv = __ldg(bias + o);
            float* eprow = ep + o * EP_STR_ + h * 32;
            #pragma unroll
            for (int c = 0; c < 32; c++) eprow[c] = __uint_as_float(r[c]) + bv;
            __syncthreads();

            #pragma unroll
            for (int j = 0; j < 8; j++) {
                int idx = tid + j * 256;
                int row = idx >> 4, c4 = idx & 15;
                float4 v = *(const float4*)(ep + row * EP_STR_ + c4 * 4);
                int e = prev_e0 + c4 * 4;
                float* po = out + ((size_t)prev_b * CO_ + row) * E_ + e;
                if (e + 3 < E_) {
                    *(float4*)po = v;
                } else {
                    if (e + 0 < E_) po[0] = v.x;
                    if (e + 1 < E_) po[1] = v.y;
                    if (e + 2 < E_) po[2] = v.z;
                    if (e + 3 < E_) po[3] = v.w;
                }
            }
        }
        prev_b = b; prev_e0 = e0; prev_i = i;
    }

    // ---- drain: epilogue for the last unit ----
    if (prev_i >= 0) {
        int pp = prev_i & 1;
        MB_WAIT_PARITY(pp ? mbar1 : mbar0, (prev_i >> 1) & 1);
        TC_FENCE_AFTER();

        int h = wid >> 2;
        int o = (wid & 3) * 32 + lane;
        uint32_t r[32];
        TC_LD_X32(r, tmem + pp * 64 + h * 32);
        TC_WAIT_LD();
        TC_FENCE_BEFORE();
        float bv = __ldg(bias + o);
        float* eprow = ep + o * EP_STR_ + h * 32;
        #pragma unroll
        for (int c = 0; c < 32; c++) eprow[c] = __uint_as_float(r[c]) + bv;
        __syncthreads();

        #pragma unroll
        for (int j = 0; j < 8; j++) {
            int idx = tid + j * 256;
            int row = idx >> 4, c4 = idx & 15;
            float4 v = *(const float4*)(ep + row * EP_STR_ + c4 * 4);
            int e = prev_e0 + c4 * 4;
            float* po = out + ((size_t)prev_b * CO_ + row) * E_ + e;
            if (e + 3 < E_) {
                *(float4*)po = v;
            } else {
                if (e + 0 < E_) po[0] = v.x;
                if (e + 1 < E_) po[1] = v.y;
                if (e + 2 < E_) po[2] = v.z;
                if (e + 3 < E_) po[3] = v.w;
            }
        }
    }

    // ---- cleanup ----
    __syncthreads();
    if (wid == 0) {
        if (elect1()) { MB_INVAL(mbar0); MB_INVAL(mbar1); }
        TC_DEALLOC(tmem, 512);
    }
#endif // TC_OK_
}

// ---------------------------------------------------------------------------
extern "C" void kernel_launch(void* const* d_in, const int* in_sizes, int n_in,
                              void* d_out, int out_size) {
    const float* x    = (const float*)d_in[0];
    const void*  gemm = d_in[1];
    const float* W    = (const float*)d_in[2];
    const float* bias = (const float*)d_in[3];
    float*       out  = (float*)d_out;

    dim3 tg((E_ + 63) / 64, B_);
    transpose_kernel<<<tg, 256>>>(x, (const unsigned int*)gemm);

    int dev = 0, nsm = 148;
    cudaGetDevice(&dev);
    cudaDeviceGetAttribute(&nsm, cudaDevAttrMultiProcessorCount, dev);
    if (nsm <= 0) nsm = 148;

    cudaFuncSetAttribute(meshconv_tc,
                         cudaFuncAttributeMaxDynamicSharedMemorySize, SMEM_SZ_);
    meshconv_tc<<<nsm, NT_, SMEM_SZ_>>>(gemm, W, bias, out);
}

// round 14
// speedup vs baseline: 1.0575x; 1.0575x over previous
#include <cuda_runtime.h>
#include <stdint.h>

// ---------------- problem constants ----------------
#define B_   8
#define F_   64
#define E_   50000
#define CO_  128
#define KK_  320         // F*5 contraction dim (kappa' = q*64 + f ordering)
#define UE_  64          // edges per pipeline unit (MMA N)
#define NT_  512         // threads per CTA (16 warps)
#define UPB_ 782         // ceil(50000/64)
#define NU_  (UPB_ * B_) // total units
#define NSTEP_ 40        // 320 / 8 (tf32 K per MMA)

#define TMEM_A_  128     // A: cols 128..447 (D: 0..127, double-buffered 64+64)
#define WS_STR_  324     // W smem staging row stride (floats)
#define HDR_     4096
#define BUF_     81920   // one G buffer: 10 K-groups * 8KB
#define EP_OFF_  (HDR_ + 2 * BUF_)          // epilogue transpose buffer
#define EP_STR_  68                          // floats per row (16B-aligned rows)
#define SMEM_SZ_ (EP_OFF_ + CO_ * EP_STR_ * 4)   // 202,752 B

// idesc kind::tf32: c=F32, a=TF32, b=TF32, N=64 (8<<17), M=128 (8<<24)
#define IDESC64_ 0x8100910u

__device__ __align__(16) float g_xt[(size_t)B_ * E_ * F_];   // x transposed (B,E,F)
__device__ int g_idx64;

#if defined(__CUDA_ARCH_FEAT_SM103_ALL)
#define TC_OK_ 1
#else
#define TC_OK_ 0
#endif

// ---------------- PTX helpers (generic) ----------------
__device__ __forceinline__ uint32_t smem_u32(const void* p) {
    uint32_t a;
    asm("{ .reg .u64 t; cvta.to.shared.u64 t, %1; cvt.u32.u64 %0, t; }" : "=r"(a) : "l"(p));
    return a;
}
__device__ __forceinline__ uint32_t elect1() {
    uint32_t p;
    asm volatile("{ .reg .pred p; elect.sync _|p, 0xFFFFFFFF; selp.b32 %0, 1, 0, p; }" : "=r"(p));
    return p;
}
__device__ __forceinline__ float f2t(float x) {
    uint32_t u;
    asm("cvt.rna.tf32.f32 %0, %1;" : "=r"(u) : "f"(x));
    return __uint_as_float(u);
}

#define MB_INIT(mb, c)    asm volatile("mbarrier.init.shared.b64 [%0], %1;" :: "r"(mb), "r"(c) : "memory")
#define MB_INVAL(mb)      asm volatile("mbarrier.inval.shared.b64 [%0];" :: "r"(mb) : "memory")

#define MB_WAIT_PARITY(mb, ph) do {                                          \
    uint32_t _m = (mb), _p = (ph), _d;                                       \
    asm volatile("{ .reg .pred p; mbarrier.try_wait.parity.acquire.cta.shared::cta.b64 p, [%1], %2; selp.b32 %0,1,0,p; }" \
                 : "=r"(_d) : "r"(_m), "r"(_p) : "memory");                  \
    if (!_d) {                                                               \
        asm volatile("{ .reg .pred P1;\n"                                    \
            "WL_%=: mbarrier.try_wait.parity.acquire.cta.shared::cta.b64 P1, [%0], %1, 0x989680;\n" \
            "@P1 bra.uni WD_%=;\n bra.uni WL_%=;\nWD_%=: }"                  \
            :: "r"(_m), "r"(_p) : "memory");                                 \
    } } while (0)

// ---------------- tcgen05 helpers (sm_103a-only) ----------------
#if TC_OK_
#define TC_ALLOC(sa, n)   asm volatile("tcgen05.alloc.cta_group::1.sync.aligned.shared::cta.b32 [%0], %1;" :: "r"(sa), "r"(n) : "memory")
#define TC_RELINQ()       asm volatile("tcgen05.relinquish_alloc_permit.cta_group::1.sync.aligned;")
#define TC_DEALLOC(t, n)  asm volatile("tcgen05.dealloc.cta_group::1.sync.aligned.b32 %0, %1;" :: "r"(t), "r"(n))
#define TC_WAIT_ST()      asm volatile("tcgen05.wait::st.sync.aligned;" ::: "memory")
#define TC_WAIT_LD()      asm volatile("tcgen05.wait::ld.sync.aligned;" ::: "memory")
#define TC_FENCE_BEFORE() asm volatile("tcgen05.fence::before_thread_sync;" ::: "memory")
#define TC_FENCE_AFTER()  asm volatile("tcgen05.fence::after_thread_sync;" ::: "memory")
#define TC_COMMIT(mb)     asm volatile("tcgen05.commit.cta_group::1.mbarrier::arrive::one.shared::cluster.b64 [%0];" :: "r"(mb) : "memory")

#define TC_ST_X32(addr, r) \
    asm volatile("tcgen05.st.sync.aligned.32x32b.x32.b32 [%0], "             \
        "{%1,%2,%3,%4,%5,%6,%7,%8,%9,%10,%11,%12,%13,%14,%15,%16,"          \
        "%17,%18,%19,%20,%21,%22,%23,%24,%25,%26,%27,%28,%29,%30,%31,%32};" \
        :: "r"(addr),                                                        \
        "r"((r)[0]),"r"((r)[1]),"r"((r)[2]),"r"((r)[3]),"r"((r)[4]),"r"((r)[5]),"r"((r)[6]),"r"((r)[7]), \
        "r"((r)[8]),"r"((r)[9]),"r"((r)[10]),"r"((r)[11]),"r"((r)[12]),"r"((r)[13]),"r"((r)[14]),"r"((r)[15]), \
        "r"((r)[16]),"r"((r)[17]),"r"((r)[18]),"r"((r)[19]),"r"((r)[20]),"r"((r)[21]),"r"((r)[22]),"r"((r)[23]), \
        "r"((r)[24]),"r"((r)[25]),"r"((r)[26]),"r"((r)[27]),"r"((r)[28]),"r"((r)[29]),"r"((r)[30]),"r"((r)[31]) \
        : "memory")

#define TC_LD_X16(r, addr) \
    asm volatile("tcgen05.ld.sync.aligned.32x32b.x16.b32 "                   \
        "{%0,%1,%2,%3,%4,%5,%6,%7,%8,%9,%10,%11,%12,%13,%14,%15}, [%16];"    \
        : "=r"((r)[0]),"=r"((r)[1]),"=r"((r)[2]),"=r"((r)[3]),               \
        "=r"((r)[4]),"=r"((r)[5]),"=r"((r)[6]),"=r"((r)[7]),                 \
        "=r"((r)[8]),"=r"((r)[9]),"=r"((r)[10]),"=r"((r)[11]),               \
        "=r"((r)[12]),"=r"((r)[13]),"=r"((r)[14]),"=r"((r)[15])              \
        : "r"(addr))

__device__ __forceinline__ void mma_tf32_ts(uint32_t d, uint32_t a, uint64_t bdesc,
                                            uint32_t idesc, bool acc) {
    uint32_t en = acc ? 1u : 0u;
    asm volatile(
        "{\n\t.reg .pred p;\n\tsetp.ne.u32 p, %5, 0;\n\t"
        "tcgen05.mma.cta_group::1.kind::tf32 [%0], [%1], %2, %3, {%4, %4, %4, %4}, p;\n\t}"
        :: "r"(d), "r"(a), "l"(bdesc), "r"(idesc), "r"(0u), "r"(en) : "memory");
}
#endif // TC_OK_

// SW128 smem descriptor: layout=SW128(2), version=1, SBO=64, LBO=1
#define DESC_BASE_ ((2ull << 61) | (1ull << 46) | (64ull << 32) | (1ull << 16))
#define MAKE_DESC(a) (DESC_BASE_ | ((uint64_t)((a) >> 4) & 0x3FFF))
#define SWZ(o) ((o) ^ (((o) >> 3) & 0x70))

// ---------------------------------------------------------------------------
// x (B,F,E) -> xt (B,E,F); block (0,0) also detects gemm dtype.
// ---------------------------------------------------------------------------
__global__ __launch_bounds__(256) void transpose_kernel(const float* __restrict__ x,
                                                        const unsigned int* __restrict__ g) {
    __shared__ float t[64 * 68];
    __shared__ int s_nz;
    int b  = blockIdx.y;
    int e0 = blockIdx.x * 64;
    int tid = threadIdx.x;

    if (blockIdx.x == 0 && blockIdx.y == 0) {
        if (tid == 0) s_nz = 0;
        __syncthreads();
        unsigned acc = 0;
        #pragma unroll
        for (int i = 0; i < 8; i++) acc |= g[(tid + i * 256) * 2 + 1];
        if (acc) atomicOr(&s_nz, 1);
        __syncthreads();
        if (tid == 0) g_idx64 = (s_nz == 0) ? 1 : 0;
        __syncthreads();
    }

    if (e0 + 64 <= E_) {
        #pragma unroll
        for (int i = 0; i < 4; i++) {
            int idx = tid + i * 256;
            int f = idx >> 4, c4 = idx & 15;
            float4 v = *(const float4*)(x + ((size_t)b * F_ + f) * E_ + e0 + c4 * 4);
            *(float4*)(&t[f * 68 + c4 * 4]) = v;
        }
        __syncthreads();
        int e  = tid & 63;
        int jb = tid >> 6;
        float* po = g_xt + ((size_t)b * E_ + e0 + e) * F_;
        #pragma unroll
        for (int jj = 0; jj < 4; jj++) {
            int j = jb + jj * 4;
            float4 v = make_float4(t[(j*4+0)*68 + e], t[(j*4+1)*68 + e],
                                   t[(j*4+2)*68 + e], t[(j*4+3)*68 + e]);
            *(float4*)(po + j * 4) = v;
        }
    } else {
        for (int idx = tid; idx < 64 * 64; idx += 256) {
            int e = e0 + (idx & 63);
            int f = idx >> 6;
            if (e < E_)
                g_xt[((size_t)b * E_ + e) * F_ + f] = x[((size_t)b * F_ + f) * E_ + e];
        }
    }
}

// ---------------------------------------------------------------------------
// Persistent pipelined tcgen05 kernel: 64-edge units, double-buffered G + D.
// 512 threads (16 warps) for latency hiding; smem pins 1 CTA/SM anyway.
// ---------------------------------------------------------------------------
__global__ __launch_bounds__(NT_, 1)
void meshconv_tc(const void*  __restrict__ gemm_raw,
                 const float* __restrict__ Wg,
                 const float* __restrict__ bias,
                 float*       __restrict__ out)
{
#if TC_OK_
    extern __shared__ char smem[];
    uint32_t sbase = smem_u32(smem);
    char*  tile = smem + HDR_;
    float* ep   = (float*)(smem + EP_OFF_);
    uint32_t mbar0 = sbase + 8;     // slot 0
    uint32_t mbar1 = sbase + 16;    // slot 1
    uint32_t gsb   = sbase + HDR_;

    const int tid = threadIdx.x, wid = tid >> 5, lane = tid & 31;
    const int idx64 = g_idx64;

    if (wid == 0) {
        TC_ALLOC(sbase, 512);
        TC_RELINQ();
        if (elect1()) { MB_INIT(mbar0, 1); MB_INIT(mbar1, 1); }
    }
    __syncthreads();
    uint32_t tmem;
    asm volatile("ld.shared.b32 %0, [%1];" : "=r"(tmem) : "r"(sbase));

    // ---- stage W: gmem -> smem (kappa = f*5+q -> kappa' = q*64+f), one pass ----
    float* ws = (float*)tile;   // spans buf0+buf1+ep region (pre-pipeline only)
    #pragma unroll 4
    for (int i = 0; i < 20; i++) {
        int idx4 = tid + i * NT_;
        int o = idx4 / 80, c4 = idx4 % 80;
        float4 v = *(const float4*)(Wg + o * KK_ + c4 * 4);
        int kk = c4 * 4;
        ws[o * WS_STR_ + ((kk    ) % 5) * 64 + (kk    ) / 5] = v.x;
        ws[o * WS_STR_ + ((kk + 1) % 5) * 64 + (kk + 1) / 5] = v.y;
        ws[o * WS_STR_ + ((kk + 2) % 5) * 64 + (kk + 2) / 5] = v.z;
        ws[o * WS_STR_ + ((kk + 3) % 5) * 64 + (kk + 3) / 5] = v.w;
    }
    __syncthreads();

    // ---- smem -> TMEM (A operand, tf32; lane = Cout row, col = kappa') ----
    if (tid < 128) {
        const float* wrow = ws + tid * WS_STR_;
        uint32_t woff = (uint32_t)(wid & 3) << 21;
        for (int g = 0; g < 10; g++) {
            uint32_t r[32];
            #pragma unroll
            for (int u = 0; u < 8; u++) {
                float4 v = *(const float4*)(wrow + g * 32 + u * 4);
                asm("cvt.rna.tf32.f32 %0, %1;" : "=r"(r[u*4+0]) : "f"(v.x));
                asm("cvt.rna.tf32.f32 %0, %1;" : "=r"(r[u*4+1]) : "f"(v.y));
                asm("cvt.rna.tf32.f32 %0, %1;" : "=r"(r[u*4+2]) : "f"(v.z));
                asm("cvt.rna.tf32.f32 %0, %1;" : "=r"(r[u*4+3]) : "f"(v.w));
            }
            TC_ST_X32(tmem + TMEM_A_ + g * 32 + woff, r);
            TC_WAIT_ST();
        }
    }
    TC_FENCE_BEFORE();
    __syncthreads();

    // ---- pipelined unit loop ----
    int prev_b = 0, prev_e0 = 0, prev_i = -1;
    int i = 0;
    for (int t = blockIdx.x; t < NU_; t += gridDim.x, i++) {
        int b  = t / UPB_;
        int e0 = (t - b * UPB_) * UE_;
        const float* xb = g_xt + (size_t)b * E_ * F_;
        int p = i & 1;
        char* buf = tile + p * BUF_;

        // ---- gather + combine -> G buffer p (tf32, SW128 atoms) ----
        // unit u = e*16 + c: 16 lanes cover one edge row -> 4 lines per LDG.
        #pragma unroll
        for (int ii = 0; ii < 2; ii++) {
            int u = tid + ii * NT_;
            int e = u >> 4, c = u & 15;
            int eg = e0 + e; if (eg > E_ - 1) eg = E_ - 1;

            int n1, n2, n3, n4;
            if (idx64) {
                const long long* gp = (const long long*)gemm_raw + ((size_t)b * E_ + eg) * 4;
                n1 = (int)gp[0]; n2 = (int)gp[1]; n3 = (int)gp[2]; n4 = (int)gp[3];
            } else {
                int4 gi = *(const int4*)((const int*)gemm_raw + ((size_t)b * E_ + eg) * 4);
                n1 = gi.x; n2 = gi.y; n3 = gi.z; n4 = gi.w;
            }

            float4 v0 = *((const float4*)(xb + (size_t)eg * F_) + c);
            float4 v1 = *((const float4*)(xb + (size_t)n1 * F_) + c);
            float4 v2 = *((const float4*)(xb + (size_t)n2 * F_) + c);
            float4 v3 = *((const float4*)(xb + (size_t)n3 * F_) + c);
            float4 v4 = *((const float4*)(xb + (size_t)n4 * F_) + c);

            float4 w0 = make_float4(f2t(v0.x), f2t(v0.y), f2t(v0.z), f2t(v0.w));
            float4 w1 = make_float4(f2t(v1.x+v3.x), f2t(v1.y+v3.y), f2t(v1.z+v3.z), f2t(v1.w+v3.w));
            float4 w2 = make_float4(f2t(v2.x+v4.x), f2t(v2.y+v4.y), f2t(v2.z+v4.z), f2t(v2.w+v4.w));
            float4 w3 = make_float4(f2t(fabsf(v1.x-v3.x)), f2t(fabsf(v1.y-v3.y)),
                                    f2t(fabsf(v1.z-v3.z)), f2t(fabsf(v1.w-v3.w)));
            float4 w4 = make_float4(f2t(fabsf(v2.x-v4.x)), f2t(fabsf(v2.y-v4.y)),
                                    f2t(fabsf(v2.z-v4.z)), f2t(fabsf(v2.w-v4.w)));

            int half = c >> 3, i4 = c & 7;
            uint32_t obase = ((uint32_t)(e >> 3) << 10) + ((uint32_t)(e & 7) << 7)
                           + ((uint32_t)i4 << 4);
            #define PUTQ(q, val) do {                                         \
                uint32_t off = obase + (uint32_t)((2*(q) + half) << 13);      \
                off = SWZ(off);                                               \
                *(float4*)(buf + off) = (val);                                \
            } while (0)
            PUTQ(0, w0); PUTQ(1, w1); PUTQ(2, w2); PUTQ(3, w3); PUTQ(4, w4);
            #undef PUTQ
        }
        asm volatile("fence.proxy.async.shared::cta;" ::: "memory");
        __syncthreads();

        // ---- issue MMA for unit i (async): D cols p*64, buffer p ----
        if (wid == 0) {
            TC_FENCE_AFTER();
            if (elect1()) {
                uint64_t bb = MAKE_DESC(gsb + (uint32_t)p * BUF_);
                #pragma unroll 1
                for (int k = 0; k < NSTEP_; k++) {
                    uint64_t bd = bb + (uint64_t)((k >> 2) * 512 + (k & 3) * 2);
                    mma_tf32_ts(tmem + p * 64, tmem + TMEM_A_ + k * 8, bd, IDESC64_, k > 0);
                }
                TC_COMMIT(p ? mbar1 : mbar0);
            }
        }

        // ---- epilogue for unit i-1 (overlaps MMA(i)) ----
        if (prev_i >= 0) {
            int pp = prev_i & 1;
            MB_WAIT_PARITY(pp ? mbar1 : mbar0, (prev_i >> 1) & 1);
            TC_FENCE_AFTER();

            int g16 = wid >> 2;                  // col group 0..3 (16 cols each)
            int o   = (wid & 3) * 32 + lane;     // Cout row (TMEM lane)
            uint32_t r[16];
            TC_LD_X16(r, tmem + pp * 64 + g16 * 16);
            TC_WAIT_LD();
            TC_FENCE_BEFORE();
            float bv = __ldg(bias + o);
            float* eprow = ep + o * EP_STR_ + g16 * 16;
            #pragma unroll
            for (int c = 0; c < 16; c++) eprow[c] = __uint_as_float(r[c]) + bv;
            __syncthreads();

            #pragma unroll
            for (int j = 0; j < 4; j++) {
                int idx = tid + j * NT_;
                int row = idx >> 4, c4 = idx & 15;
                float4 v = *(const float4*)(ep + row * EP_STR_ + c4 * 4);
                int e = prev_e0 + c4 * 4;
                float* po = out + ((size_t)prev_b * CO_ + row) * E_ + e;
                if (e + 3 < E_) {
                    *(float4*)po = v;
                } else {
                    if (e + 0 < E_) po[0] = v.x;
                    if (e + 1 < E_) po[1] = v.y;
                    if (e + 2 < E_) po[2] = v.z;
                    if (e + 3 < E_) po[3] = v.w;
                }
            }
        }
        prev_b = b; prev_e0 = e0; prev_i = i;
    }

    // ---- drain: epilogue for the last unit ----
    if (prev_i >= 0) {
        int pp = prev_i & 1;
        MB_WAIT_PARITY(pp ? mbar1 : mbar0, (prev_i >> 1) & 1);
        TC_FENCE_AFTER();

        int g16 = wid >> 2;
        int o   = (wid & 3) * 32 + lane;
        uint32_t r[16];
        TC_LD_X16(r, tmem + pp * 64 + g16 * 16);
        TC_WAIT_LD();
        TC_FENCE_BEFORE();
        float bv = __ldg(bias + o);
        float* eprow = ep + o * EP_STR_ + g16 * 16;
        #pragma unroll
        for (int c = 0; c < 16; c++) eprow[c] = __uint_as_float(r[c]) + bv;
        __syncthreads();

        #pragma unroll
        for (int j = 0; j < 4; j++) {
            int idx = tid + j * NT_;
            int row = idx >> 4, c4 = idx & 15;
            float4 v = *(const float4*)(ep + row * EP_STR_ + c4 * 4);
            int e = prev_e0 + c4 * 4;
            float* po = out + ((size_t)prev_b * CO_ + row) * E_ + e;
            if (e + 3 < E_) {
                *(float4*)po = v;
            } else {
                if (e + 0 < E_) po[0] = v.x;
                if (e + 1 < E_) po[1] = v.y;
                if (e + 2 < E_) po[2] = v.z;
                if (e + 3 < E_) po[3] = v.w;
            }
        }
    }

    // ---- cleanup ----
    __syncthreads();
    if (wid == 0) {
        if (elect1()) { MB_INVAL(mbar0); MB_INVAL(mbar1); }
        TC_DEALLOC(tmem, 512);
    }
#endif // TC_OK_
}

// ---------------------------------------------------------------------------
extern "C" void kernel_launch(void* const* d_in, const int* in_sizes, int n_in,
                              void* d_out, int out_size) {
    const float* x    = (const float*)d_in[0];
    const void*  gemm = d_in[1];
    const float* W    = (const float*)d_in[2];
    const float* bias = (const float*)d_in[3];
    float*       out  = (float*)d_out;

    dim3 tg((E_ + 63) / 64, B_);
    transpose_kernel<<<tg, 256>>>(x, (const unsigned int*)gemm);

    int dev = 0, nsm = 148;
    cudaGetDevice(&dev);
    cudaDeviceGetAttribute(&nsm, cudaDevAttrMultiProcessorCount, dev);
    if (nsm <= 0) nsm = 148;

    cudaFuncSetAttribute(meshconv_tc,
                         cudaFuncAttributeMaxDynamicSharedMemorySize, SMEM_SZ_);
    meshconv_tc<<<nsm, NT_, SMEM_SZ_>>>(gemm, W, bias, out);
}

// round 15
// speedup vs baseline: 1.3244x; 1.2524x over previous
#include <cuda_runtime.h>
#include <stdint.h>

// ---------------- problem constants ----------------
#define B_   8
#define F_   64
#define E_   50000
#define CO_  128
#define KK_  320
#define UE_  64          // edges per pipeline unit (MMA N)
#define NT_  512         // threads per CTA (16 warps)
#define UPB_ 782         // ceil(50000/64)
#define NU_  (UPB_ * B_)
#define NSTEP_ 40        // 320 / 8 (tf32 K per MMA)

#define TMEM_A_  128     // A: cols 128..447; D buffers: 0, 64, 448
#define WS_STR_  324
#define HDR_     4096
#define BUF_     81920   // one G buffer
#define EP_OFF_  (HDR_ + 2 * BUF_)
#define EP_STR_  68      // floats per ep row (272B, 16B-aligned)
#define SMEM_SZ_ (EP_OFF_ + CO_ * EP_STR_ * 4)   // 202,752 B

// idesc kind::tf32: c=F32, a=TF32, b=TF32, N=64, M=128
#define IDESC64_ 0x8100910u

__device__ __align__(16) float g_xt[(size_t)B_ * E_ * F_];
__device__ int g_idx64;

#if defined(__CUDA_ARCH_FEAT_SM103_ALL)
#define TC_OK_ 1
#else
#define TC_OK_ 0
#endif

// ---------------- PTX helpers (generic) ----------------
__device__ __forceinline__ uint32_t smem_u32(const void* p) {
    uint32_t a;
    asm("{ .reg .u64 t; cvta.to.shared.u64 t, %1; cvt.u32.u64 %0, t; }" : "=r"(a) : "l"(p));
    return a;
}
__device__ __forceinline__ uint32_t elect1() {
    uint32_t p;
    asm volatile("{ .reg .pred p; elect.sync _|p, 0xFFFFFFFF; selp.b32 %0, 1, 0, p; }" : "=r"(p));
    return p;
}
__device__ __forceinline__ float f2t(float x) {
    uint32_t u;
    asm("cvt.rna.tf32.f32 %0, %1;" : "=r"(u) : "f"(x));
    return __uint_as_float(u);
}

#define MB_INIT(mb, c)    asm volatile("mbarrier.init.shared.b64 [%0], %1;" :: "r"(mb), "r"(c) : "memory")
#define MB_INVAL(mb)      asm volatile("mbarrier.inval.shared.b64 [%0];" :: "r"(mb) : "memory")

#define MB_WAIT_PARITY(mb, ph) do {                                          \
    uint32_t _m = (mb), _p = (ph), _d;                                       \
    asm volatile("{ .reg .pred p; mbarrier.try_wait.parity.acquire.cta.shared::cta.b64 p, [%1], %2; selp.b32 %0,1,0,p; }" \
                 : "=r"(_d) : "r"(_m), "r"(_p) : "memory");                  \
    if (!_d) {                                                               \
        asm volatile("{ .reg .pred P1;\n"                                    \
            "WL_%=: mbarrier.try_wait.parity.acquire.cta.shared::cta.b64 P1, [%0], %1, 0x989680;\n" \
            "@P1 bra.uni WD_%=;\n bra.uni WL_%=;\nWD_%=: }"                  \
            :: "r"(_m), "r"(_p) : "memory");                                 \
    } } while (0)

// ---------------- tcgen05 helpers (sm_103a-only) ----------------
#if TC_OK_
#define TC_ALLOC(sa, n)   asm volatile("tcgen05.alloc.cta_group::1.sync.aligned.shared::cta.b32 [%0], %1;" :: "r"(sa), "r"(n) : "memory")
#define TC_RELINQ()       asm volatile("tcgen05.relinquish_alloc_permit.cta_group::1.sync.aligned;")
#define TC_DEALLOC(t, n)  asm volatile("tcgen05.dealloc.cta_group::1.sync.aligned.b32 %0, %1;" :: "r"(t), "r"(n))
#define TC_WAIT_ST()      asm volatile("tcgen05.wait::st.sync.aligned;" ::: "memory")
#define TC_WAIT_LD()      asm volatile("tcgen05.wait::ld.sync.aligned;" ::: "memory")
#define TC_FENCE_BEFORE() asm volatile("tcgen05.fence::before_thread_sync;" ::: "memory")
#define TC_FENCE_AFTER()  asm volatile("tcgen05.fence::after_thread_sync;" ::: "memory")
#define TC_COMMIT(mb)     asm volatile("tcgen05.commit.cta_group::1.mbarrier::arrive::one.shared::cluster.b64 [%0];" :: "r"(mb) : "memory")

#define TC_ST_X32(addr, r) \
    asm volatile("tcgen05.st.sync.aligned.32x32b.x32.b32 [%0], "             \
        "{%1,%2,%3,%4,%5,%6,%7,%8,%9,%10,%11,%12,%13,%14,%15,%16,"          \
        "%17,%18,%19,%20,%21,%22,%23,%24,%25,%26,%27,%28,%29,%30,%31,%32};" \
        :: "r"(addr),                                                        \
        "r"((r)[0]),"r"((r)[1]),"r"((r)[2]),"r"((r)[3]),"r"((r)[4]),"r"((r)[5]),"r"((r)[6]),"r"((r)[7]), \
        "r"((r)[8]),"r"((r)[9]),"r"((r)[10]),"r"((r)[11]),"r"((r)[12]),"r"((r)[13]),"r"((r)[14]),"r"((r)[15]), \
        "r"((r)[16]),"r"((r)[17]),"r"((r)[18]),"r"((r)[19]),"r"((r)[20]),"r"((r)[21]),"r"((r)[22]),"r"((r)[23]), \
        "r"((r)[24]),"r"((r)[25]),"r"((r)[26]),"r"((r)[27]),"r"((r)[28]),"r"((r)[29]),"r"((r)[30]),"r"((r)[31]) \
        : "memory")

#define TC_LD_X16(r, addr) \
    asm volatile("tcgen05.ld.sync.aligned.32x32b.x16.b32 "                   \
        "{%0,%1,%2,%3,%4,%5,%6,%7,%8,%9,%10,%11,%12,%13,%14,%15}, [%16];"    \
        : "=r"((r)[0]),"=r"((r)[1]),"=r"((r)[2]),"=r"((r)[3]),               \
        "=r"((r)[4]),"=r"((r)[5]),"=r"((r)[6]),"=r"((r)[7]),                 \
        "=r"((r)[8]),"=r"((r)[9]),"=r"((r)[10]),"=r"((r)[11]),               \
        "=r"((r)[12]),"=r"((r)[13]),"=r"((r)[14]),"=r"((r)[15])              \
        : "r"(addr))

__device__ __forceinline__ void mma_tf32_ts(uint32_t d, uint32_t a, uint64_t bdesc,
                                            uint32_t idesc, bool acc) {
    uint32_t en = acc ? 1u : 0u;
    asm volatile(
        "{\n\t.reg .pred p;\n\tsetp.ne.u32 p, %5, 0;\n\t"
        "tcgen05.mma.cta_group::1.kind::tf32 [%0], [%1], %2, %3, {%4, %4, %4, %4}, p;\n\t}"
        :: "r"(d), "r"(a), "l"(bdesc), "r"(idesc), "r"(0u), "r"(en) : "memory");
}
#endif // TC_OK_

#define DESC_BASE_ ((2ull << 61) | (1ull << 46) | (64ull << 32) | (1ull << 16))
#define MAKE_DESC(a) (DESC_BASE_ | ((uint64_t)((a) >> 4) & 0x3FFF))
#define SWZ(o) ((o) ^ (((o) >> 3) & 0x70))

// ---------------------------------------------------------------------------
// x (B,F,E) -> xt (B,E,F); block (0,0) also detects gemm dtype.
// ---------------------------------------------------------------------------
__global__ __launch_bounds__(256) void transpose_kernel(const float* __restrict__ x,
                                                        const unsigned int* __restrict__ g) {
    __shared__ float t[64 * 68];
    __shared__ int s_nz;
    int b  = blockIdx.y;
    int e0 = blockIdx.x * 64;
    int tid = threadIdx.x;

    if (blockIdx.x == 0 && blockIdx.y == 0) {
        if (tid == 0) s_nz = 0;
        __syncthreads();
        unsigned acc = 0;
        #pragma unroll
        for (int i = 0; i < 8; i++) acc |= g[(tid + i * 256) * 2 + 1];
        if (acc) atomicOr(&s_nz, 1);
        __syncthreads();
        if (tid == 0) g_idx64 = (s_nz == 0) ? 1 : 0;
        __syncthreads();
    }

    if (e0 + 64 <= E_) {
        #pragma unroll
        for (int i = 0; i < 4; i++) {
            int idx = tid + i * 256;
            int f = idx >> 4, c4 = idx & 15;
            float4 v = *(const float4*)(x + ((size_t)b * F_ + f) * E_ + e0 + c4 * 4);
            *(float4*)(&t[f * 68 + c4 * 4]) = v;
        }
        __syncthreads();
        int e  = tid & 63;
        int jb = tid >> 6;
        float* po = g_xt + ((size_t)b * E_ + e0 + e) * F_;
        #pragma unroll
        for (int jj = 0; jj < 4; jj++) {
            int j = jb + jj * 4;
            float4 v = make_float4(t[(j*4+0)*68 + e], t[(j*4+1)*68 + e],
                                   t[(j*4+2)*68 + e], t[(j*4+3)*68 + e]);
            *(float4*)(po + j * 4) = v;
        }
    } else {
        for (int idx = tid; idx < 64 * 64; idx += 256) {
            int e = e0 + (idx & 63);
            int f = idx >> 6;
            if (e < E_)
                g_xt[((size_t)b * E_ + e) * F_ + f] = x[((size_t)b * F_ + f) * E_ + e];
        }
    }
}

// ---------------------------------------------------------------------------
// Persistent pipelined tcgen05 kernel: 3-stage rotation (gather i / MMA i /
// epilogue i-2), TMEM D triple-buffered, idx prefetch, batched gather LDGs.
// ---------------------------------------------------------------------------
__global__ __launch_bounds__(NT_, 1)
void meshconv_tc(const void*  __restrict__ gemm_raw,
                 const float* __restrict__ Wg,
                 const float* __restrict__ bias,
                 float*       __restrict__ out)
{
#if TC_OK_
    extern __shared__ char smem[];
    uint32_t sbase = smem_u32(smem);
    char*  tile = smem + HDR_;
    float* ep   = (float*)(smem + EP_OFF_);
    uint32_t gsb = sbase + HDR_;

    const int tid = threadIdx.x, wid = tid >> 5, lane = tid & 31;
    const int idx64 = g_idx64;

    if (wid == 0) {
        TC_ALLOC(sbase, 512);
        TC_RELINQ();
        if (elect1()) {
            MB_INIT(sbase + 8, 1); MB_INIT(sbase + 16, 1); MB_INIT(sbase + 24, 1);
        }
    }
    __syncthreads();
    uint32_t tmem;
    asm volatile("ld.shared.b32 %0, [%1];" : "=r"(tmem) : "r"(sbase));

    // ---- stage W: gmem -> smem (kappa = f*5+q -> kappa' = q*64+f) ----
    float* ws = (float*)tile;
    #pragma unroll 4
    for (int i = 0; i < 20; i++) {
        int idx4 = tid + i * NT_;
        int o = idx4 / 80, c4 = idx4 % 80;
        float4 v = *(const float4*)(Wg + o * KK_ + c4 * 4);
        int kk = c4 * 4;
        ws[o * WS_STR_ + ((kk    ) % 5) * 64 + (kk    ) / 5] = v.x;
        ws[o * WS_STR_ + ((kk + 1) % 5) * 64 + (kk + 1) / 5] = v.y;
        ws[o * WS_STR_ + ((kk + 2) % 5) * 64 + (kk + 2) / 5] = v.z;
        ws[o * WS_STR_ + ((kk + 3) % 5) * 64 + (kk + 3) / 5] = v.w;
    }
    __syncthreads();

    // ---- smem -> TMEM (A operand, tf32) ----
    if (tid < 128) {
        const float* wrow = ws + tid * WS_STR_;
        uint32_t woff = (uint32_t)(wid & 3) << 21;
        for (int g = 0; g < 10; g++) {
            uint32_t r[32];
            #pragma unroll
            for (int u = 0; u < 8; u++) {
                float4 v = *(const float4*)(wrow + g * 32 + u * 4);
                asm("cvt.rna.tf32.f32 %0, %1;" : "=r"(r[u*4+0]) : "f"(v.x));
                asm("cvt.rna.tf32.f32 %0, %1;" : "=r"(r[u*4+1]) : "f"(v.y));
                asm("cvt.rna.tf32.f32 %0, %1;" : "=r"(r[u*4+2]) : "f"(v.z));
                asm("cvt.rna.tf32.f32 %0, %1;" : "=r"(r[u*4+3]) : "f"(v.w));
            }
            TC_ST_X32(tmem + TMEM_A_ + g * 32 + woff, r);
            TC_WAIT_ST();
        }
    }
    TC_FENCE_BEFORE();
    __syncthreads();

    // ---- per-thread constants ----
    const int c    = tid & 15;           // float4-chunk (same for both sub-units)
    const int eA   = tid >> 4;           // edge 0..31 (sub-unit 0); sub 1 = eA+32
    const int half = c >> 3, i4 = c & 7;
    const uint32_t swzA = SWZ(((uint32_t)(eA >> 3) << 10) + ((uint32_t)(eA & 7) << 7) + ((uint32_t)i4 << 4));
    const int eB   = eA + 32;
    const uint32_t swzB = SWZ(((uint32_t)(eB >> 3) << 10) + ((uint32_t)(eB & 7) << 7) + ((uint32_t)i4 << 4));
    const int g16  = wid >> 2;           // epilogue col group
    const int orow = (wid & 3) * 32 + lane;
    const float bv = __ldg(bias + orow);
    float* eprow   = ep + orow * EP_STR_ + g16 * 16;

    // ---- prefetch idx for first unit ----
    int cur_eg[2]; int cur_n[2][4];
    int t0 = blockIdx.x;
    {
        int b = t0 / UPB_, e0 = (t0 - b * UPB_) * UE_;
        #pragma unroll
        for (int ii = 0; ii < 2; ii++) {
            int eg = e0 + eA + ii * 32; if (eg > E_ - 1) eg = E_ - 1;
            cur_eg[ii] = eg;
            if (idx64) {
                const long long* gp = (const long long*)gemm_raw + ((size_t)b * E_ + eg) * 4;
                cur_n[ii][0]=(int)gp[0]; cur_n[ii][1]=(int)gp[1]; cur_n[ii][2]=(int)gp[2]; cur_n[ii][3]=(int)gp[3];
            } else {
                int4 gi = *(const int4*)((const int*)gemm_raw + ((size_t)b * E_ + eg) * 4);
                cur_n[ii][0]=gi.x; cur_n[ii][1]=gi.y; cur_n[ii][2]=gi.z; cur_n[ii][3]=gi.w;
            }
        }
    }

    int pb[2], pe[2];                    // (b, e0) ring for epilogue lag-2
    int i = 0;
    for (int t = blockIdx.x; t < NU_; t += gridDim.x, i++) {
        int b  = t / UPB_;
        int e0 = (t - b * UPB_) * UE_;
        const float* xb = g_xt + (size_t)b * E_ * F_;

        // ======== Phase A ========
        // 1) issue all gather loads for unit i (latency spans phase A+sync)
        float4 v[2][5];
        #pragma unroll
        for (int ii = 0; ii < 2; ii++) {
            v[ii][0] = *((const float4*)(xb + (size_t)cur_eg[ii]   * F_) + c);
            v[ii][1] = *((const float4*)(xb + (size_t)cur_n[ii][0] * F_) + c);
            v[ii][2] = *((const float4*)(xb + (size_t)cur_n[ii][1] * F_) + c);
            v[ii][3] = *((const float4*)(xb + (size_t)cur_n[ii][2] * F_) + c);
            v[ii][4] = *((const float4*)(xb + (size_t)cur_n[ii][3] * F_) + c);
        }

        // 2) prefetch idx for unit i+1
        int nxt_eg[2], nxt_n[2][4];
        int tn = t + gridDim.x;
        if (tn < NU_) {
            int nb = tn / UPB_, ne0 = (tn - nb * UPB_) * UE_;
            #pragma unroll
            for (int ii = 0; ii < 2; ii++) {
                int eg = ne0 + eA + ii * 32; if (eg > E_ - 1) eg = E_ - 1;
                nxt_eg[ii] = eg;
                if (idx64) {
                    const long long* gp = (const long long*)gemm_raw + ((size_t)nb * E_ + eg) * 4;
                    nxt_n[ii][0]=(int)gp[0]; nxt_n[ii][1]=(int)gp[1]; nxt_n[ii][2]=(int)gp[2]; nxt_n[ii][3]=(int)gp[3];
                } else {
                    int4 gi = *(const int4*)((const int*)gemm_raw + ((size_t)nb * E_ + eg) * 4);
                    nxt_n[ii][0]=gi.x; nxt_n[ii][1]=gi.y; nxt_n[ii][2]=gi.z; nxt_n[ii][3]=gi.w;
                }
            }
        }

        // 3) epilogue part 1 for unit i-2: wait MMA, LDTM, bias, ep-write
        if (i >= 2) {
            int j = i - 2, s = j % 3;
            MB_WAIT_PARITY(sbase + 8 + s * 8, (j / 3) & 1);
            TC_FENCE_AFTER();
            uint32_t doff = (s == 0) ? 0u : (s == 1) ? 64u : 448u;
            uint32_t r[16];
            TC_LD_X16(r, tmem + doff + g16 * 16);
            TC_WAIT_LD();
            #pragma unroll
            for (int q = 0; q < 4; q++) {
                float4 w = make_float4(__uint_as_float(r[4*q+0]) + bv,
                                       __uint_as_float(r[4*q+1]) + bv,
                                       __uint_as_float(r[4*q+2]) + bv,
                                       __uint_as_float(r[4*q+3]) + bv);
                *(float4*)(eprow + 4 * q) = w;
            }
        }
        __syncthreads();

        // ======== Phase B ========
        // 4) epilogue part 2 for unit i-2: ep-read + STG (overlaps LDG arrivals)
        if (i >= 2) {
            int jb2 = pb[i & 1], je0 = pe[i & 1];
            #pragma unroll
            for (int j4 = 0; j4 < 4; j4++) {
                int idx = tid + j4 * NT_;
                int row = idx >> 4, c4 = idx & 15;
                float4 w = *(const float4*)(ep + row * EP_STR_ + c4 * 4);
                int e = je0 + c4 * 4;
                float* po = out + ((size_t)jb2 * CO_ + row) * E_ + e;
                if (e + 3 < E_) {
                    *(float4*)po = w;
                } else {
                    if (e + 0 < E_) po[0] = w.x;
                    if (e + 1 < E_) po[1] = w.y;
                    if (e + 2 < E_) po[2] = w.z;
                    if (e + 3 < E_) po[3] = w.w;
                }
            }
        }

        // 5) combine + STS for unit i
        char* buf = tile + (i & 1) * BUF_;
        #pragma unroll
        for (int ii = 0; ii < 2; ii++) {
            float4 v0 = v[ii][0], v1 = v[ii][1], v2 = v[ii][2], v3 = v[ii][3], v4 = v[ii][4];
            float4 w0 = make_float4(f2t(v0.x), f2t(v0.y), f2t(v0.z), f2t(v0.w));
            float4 w1 = make_float4(f2t(v1.x+v3.x), f2t(v1.y+v3.y), f2t(v1.z+v3.z), f2t(v1.w+v3.w));
            float4 w2 = make_float4(f2t(v2.x+v4.x), f2t(v2.y+v4.y), f2t(v2.z+v4.z), f2t(v2.w+v4.w));
            float4 w3 = make_float4(f2t(fabsf(v1.x-v3.x)), f2t(fabsf(v1.y-v3.y)),
                                    f2t(fabsf(v1.z-v3.z)), f2t(fabsf(v1.w-v3.w)));
            float4 w4 = make_float4(f2t(fabsf(v2.x-v4.x)), f2t(fabsf(v2.y-v4.y)),
                                    f2t(fabsf(v2.z-v4.z)), f2t(fabsf(v2.w-v4.w)));
            uint32_t sb = ii ? swzB : swzA;
            *(float4*)(buf + sb + (uint32_t)((0 + half) << 13)) = w0;
            *(float4*)(buf + sb + (uint32_t)((2 + half) << 13)) = w1;
            *(float4*)(buf + sb + (uint32_t)((4 + half) << 13)) = w2;
            *(float4*)(buf + sb + (uint32_t)((6 + half) << 13)) = w3;
            *(float4*)(buf + sb + (uint32_t)((8 + half) << 13)) = w4;
        }
        asm volatile("fence.proxy.async.shared::cta;" ::: "memory");
        __syncthreads();

        // 6) MMA issue for unit i -> D buffer i%3
        if (wid == 0) {
            TC_FENCE_AFTER();
            if (elect1()) {
                int s = i % 3;
                uint32_t doff = (s == 0) ? 0u : (s == 1) ? 64u : 448u;
                uint64_t bb = MAKE_DESC(gsb + (uint32_t)(i & 1) * BUF_);
                #pragma unroll 1
                for (int k = 0; k < NSTEP_; k++) {
                    uint64_t bd = bb + (uint64_t)((k >> 2) * 512 + (k & 3) * 2);
                    mma_tf32_ts(tmem + doff, tmem + TMEM_A_ + k * 8, bd, IDESC64_, k > 0);
                }
                TC_COMMIT(sbase + 8 + s * 8);
            }
        }

        // rotate rings
        pb[i & 1] = b; pe[i & 1] = e0;
        #pragma unroll
        for (int ii = 0; ii < 2; ii++) {
            cur_eg[ii] = nxt_eg[ii];
            cur_n[ii][0]=nxt_n[ii][0]; cur_n[ii][1]=nxt_n[ii][1];
            cur_n[ii][2]=nxt_n[ii][2]; cur_n[ii][3]=nxt_n[ii][3];
        }
    }

    // ---- drain: epilogues for the last two units ----
    for (int j = i - 2; j < i; j++) {
        if (j < 0) continue;
        int s = j % 3;
        MB_WAIT_PARITY(sbase + 8 + s * 8, (j / 3) & 1);
        TC_FENCE_AFTER();
        uint32_t doff = (s == 0) ? 0u : (s == 1) ? 64u : 448u;
        uint32_t r[16];
        TC_LD_X16(r, tmem + doff + g16 * 16);
        TC_WAIT_LD();
        #pragma unroll
        for (int q = 0; q < 4; q++) {
            float4 w = make_float4(__uint_as_float(r[4*q+0]) + bv,
                                   __uint_as_float(r[4*q+1]) + bv,
                                   __uint_as_float(r[4*q+2]) + bv,
                                   __uint_as_float(r[4*q+3]) + bv);
            *(float4*)(eprow + 4 * q) = w;
        }
        __syncthreads();
        int jb2 = pb[j & 1], je0 = pe[j & 1];
        #pragma unroll
        for (int j4 = 0; j4 < 4; j4++) {
            int idx = tid + j4 * NT_;
            int row = idx >> 4, c4 = idx & 15;
            float4 w = *(const float4*)(ep + row * EP_STR_ + c4 * 4);
            int e = je0 + c4 * 4;
            float* po = out + ((size_t)jb2 * CO_ + row) * E_ + e;
            if (e + 3 < E_) {
                *(float4*)po = w;
            } else {
                if (e + 0 < E_) po[0] = w.x;
                if (e + 1 < E_) po[1] = w.y;
                if (e + 2 < E_) po[2] = w.z;
                if (e + 3 < E_) po[3] = w.w;
            }
        }
        __syncthreads();
    }

    // ---- cleanup ----
    __syncthreads();
    if (wid == 0) {
        if (elect1()) {
            MB_INVAL(sbase + 8); MB_INVAL(sbase + 16); MB_INVAL(sbase + 24);
        }
        TC_DEALLOC(tmem, 512);
    }
#endif // TC_OK_
}

// ---------------------------------------------------------------------------
extern "C" void kernel_launch(void* const* d_in, const int* in_sizes, int n_in,
                              void* d_out, int out_size) {
    const float* x    = (const float*)d_in[0];
    const void*  gemm = d_in[1];
    const float* W    = (const float*)d_in[2];
    const float* bias = (const float*)d_in[3];
    float*       out  = (float*)d_out;

    dim3 tg((E_ + 63) / 64, B_);
    transpose_kernel<<<tg, 256>>>(x, (const unsigned int*)gemm);

    int dev = 0, nsm = 148;
    cudaGetDevice(&dev);
    cudaDeviceGetAttribute(&nsm, cudaDevAttrMultiProcessorCount, dev);
    if (nsm <= 0) nsm = 148;

    cudaFuncSetAttribute(meshconv_tc,
                         cudaFuncAttributeMaxDynamicSharedMemorySize, SMEM_SZ_);
    meshconv_tc<<<nsm, NT_, SMEM_SZ_>>>(gemm, W, bias, out);
}